// round 4
// baseline (speedup 1.0000x reference)
#include <cuda_runtime.h>
#include <math.h>

#define TILE      32
#define HALO      5
#define RAW       (TILE + 2*HALO)   /* 42 */
#define HP        33                /* odd pitch -> conflict-free vertical reads */
#define NTHREADS  256

typedef unsigned long long u64;

// Per-block partial sums (deterministic: each block writes exactly one slot).
__device__ float g_blockSums[65536];
__device__ unsigned int g_count = 0;

// Normalized 1D Gaussian, size 11, sigma 1.5 (matches cv2.getGaussianKernel).
__device__ __forceinline__ float gw(int t) {
    constexpr float G[11] = {
        0.00102838f, 0.00759876f, 0.03600077f, 0.10936069f, 0.21300553f,
        0.26601172f,
        0.21300553f, 0.10936069f, 0.03600077f, 0.00759876f, 0.00102838f };
    return G[t];
}
// index of unique weight (kernel symmetric): 0..5
__device__ __forceinline__ int wux(int t) { return t <= 5 ? t : 10 - t; }

// packed duplicated weights in constant memory (keeps them out of registers;
// LDC is cheap and rematerializable under register pressure)
__constant__ float2 cGW2[6] = {
    {0.00102838f, 0.00102838f}, {0.00759876f, 0.00759876f},
    {0.03600077f, 0.03600077f}, {0.10936069f, 0.10936069f},
    {0.21300553f, 0.21300553f}, {0.26601172f, 0.26601172f} };

__device__ __forceinline__ u64 ldw2(int t) {
    return *reinterpret_cast<const u64*>(&cGW2[wux(t)]);
}

// ---- packed f32x2 helpers (Blackwell) ----
__device__ __forceinline__ u64 pack2(float lo, float hi) {
    u64 r; asm("mov.b64 %0, {%1, %2};" : "=l"(r) : "f"(lo), "f"(hi)); return r;
}
__device__ __forceinline__ void unpack2(u64 v, float& lo, float& hi) {
    asm("mov.b64 {%0, %1}, %2;" : "=f"(lo), "=f"(hi) : "l"(v));
}
__device__ __forceinline__ u64 mul2(u64 a, u64 b) {
    u64 d; asm("mul.rn.f32x2 %0, %1, %2;" : "=l"(d) : "l"(a), "l"(b)); return d;
}
__device__ __forceinline__ u64 fma2(u64 a, u64 b, u64 c) {
    u64 d; asm("fma.rn.f32x2 %0, %1, %2, %3;" : "=l"(d) : "l"(a), "l"(b), "l"(c)); return d;
}

// Horizontal 11-tap blur of (x, y, xx, yy, xy) read straight from gmem.
// CLAMP=false: interior tile, unclamped indices (fast path, 99.7% of blocks).
template<bool CLAMP>
__device__ __forceinline__ void hpass(const float* __restrict__ img1,
                                      const float* __restrict__ img2,
                                      int W, int H, int bx, int by, int tid,
                                      u64 (*hs_mu)[HP], u64 (*hs_sq)[HP],
                                      float (*hs_xy)[HP])
{
    for (int i = tid; i < RAW * 8; i += NTHREADS) {
        const int r = i >> 3;
        const int g = (i & 7) << 2;   // output cols g..g+3, window cols g..g+13

        int gy = by - HALO + r;
        if (CLAMP) gy = min(max(gy, 0), H - 1);
        const float* __restrict__ p1 = img1 + (size_t)gy * (size_t)W;
        const float* __restrict__ p2 = img2 + (size_t)gy * (size_t)W;
        const int gx0 = bx - HALO + g;

        u64   amu[4] = {0ull, 0ull, 0ull, 0ull};
        u64   asq[4] = {0ull, 0ull, 0ull, 0ull};
        float axy[4] = {0.f, 0.f, 0.f, 0.f};

        #pragma unroll
        for (int k = 0; k < 14; k++) {
            int gx = gx0 + k;
            if (CLAMP) gx = min(max(gx, 0), W - 1);
            const float vx = __ldg(p1 + gx);
            const float vy = __ldg(p2 + gx);
            const u64   v2  = pack2(vx, vy);
            const u64   sq2 = mul2(v2, v2);
            const float xy  = vx * vy;
            #pragma unroll
            for (int o = 0; o < 4; o++) {
                const int t = k - o;
                if (t >= 0 && t < 11) {
                    const u64 w2 = ldw2(t);
                    amu[o] = fma2(v2,  w2, amu[o]);
                    asq[o] = fma2(sq2, w2, asq[o]);
                    axy[o] = fmaf(xy, gw(t), axy[o]);
                }
            }
        }
        #pragma unroll
        for (int o = 0; o < 4; o++) {
            hs_mu[r][g + o] = amu[o];
            hs_sq[r][g + o] = asq[o];
            hs_xy[r][g + o] = axy[o];
        }
    }
}

__global__ __launch_bounds__(NTHREADS, 6)
void ssim_tile_kernel(const float* __restrict__ img1,
                      const float* __restrict__ img2,
                      int W, int H, int nBlocks, double inv_n,
                      float* __restrict__ out)
{
    __shared__ u64   hs_mu[RAW][HP];   // packed (hblur(x),  hblur(y))
    __shared__ u64   hs_sq[RAW][HP];   // packed (hblur(xx), hblur(yy))
    __shared__ float hs_xy[RAW][HP];   // hblur(xy)
    __shared__ float wsum[NTHREADS / 32];
    __shared__ bool  isLast;

    const int tid = threadIdx.x;
    const int bx = blockIdx.x * TILE;
    const int by = blockIdx.y * TILE;

    // ---------------- horizontal pass (direct from gmem) ----------------
    const bool interior = (bx >= HALO) && (by >= HALO) &&
                          (bx + TILE + HALO <= W) && (by + TILE + HALO <= H);
    if (interior) hpass<false>(img1, img2, W, H, bx, by, tid, hs_mu, hs_sq, hs_xy);
    else          hpass<true >(img1, img2, W, H, bx, by, tid, hs_mu, hs_sq, hs_xy);
    __syncthreads();

    // ---------------- vertical pass + SSIM: 32 cols x 8 row-groups of 4 rows --------
    float lsum = 0.f;
    {
        const int c  = tid & 31;
        const int r0 = (tid >> 5) * 4;   // output rows r0..r0+3

        u64   vmu[4] = {0ull, 0ull, 0ull, 0ull};
        u64   vsq[4] = {0ull, 0ull, 0ull, 0ull};
        float vxy[4] = {0.f, 0.f, 0.f, 0.f};

        #pragma unroll
        for (int j = 0; j < 14; j++) {
            const u64   m = hs_mu[r0 + j][c];
            const u64   s = hs_sq[r0 + j][c];
            const float p = hs_xy[r0 + j][c];
            #pragma unroll
            for (int o = 0; o < 4; o++) {
                const int t = j - o;
                if (t >= 0 && t < 11) {
                    const u64 w2 = ldw2(t);
                    vmu[o] = fma2(m, w2, vmu[o]);
                    vsq[o] = fma2(s, w2, vsq[o]);
                    vxy[o] = fmaf(p, gw(t), vxy[o]);
                }
            }
        }

        const float C1 = 6.5025f;    // (0.01*255)^2
        const float C2 = 58.5225f;   // (0.03*255)^2
        const float SCALE = 0.000244140625f;  // 2^-12: keep 4-products in range

        float nn[4], dd[4];
        #pragma unroll
        for (int o = 0; o < 4; o++) {
            if (by + r0 + o < H && bx + c < W) {
                float mu1, mu2, exx, eyy;
                unpack2(vmu[o], mu1, mu2);
                unpack2(vsq[o], exx, eyy);
                const float exy = vxy[o];
                const float m11 = mu1 * mu1;
                const float m22 = mu2 * mu2;
                const float m12 = mu1 * mu2;
                const float s1q = exx - m11;
                const float s2q = eyy - m22;
                const float s12 = exy - m12;
                nn[o] = ((2.f * m12 + C1) * SCALE) * ((2.f * s12 + C2) * SCALE);
                dd[o] = ((m11 + m22 + C1) * SCALE) * ((s1q + s2q + C2) * SCALE);
            } else {
                nn[o] = 0.f;
                dd[o] = 1.f;
            }
        }
        // sum_i n_i/d_i = (sum_i n_i * prod_{j!=i} d_j) / prod_j d_j  -> one RCP / 4 px
        const float d01 = dd[0] * dd[1];
        const float d23 = dd[2] * dd[3];
        const float D   = d01 * d23;
        const float s01 = fmaf(nn[0], dd[1], nn[1] * dd[0]);
        const float s23 = fmaf(nn[2], dd[3], nn[3] * dd[2]);
        const float S   = fmaf(s01, d23, s23 * d01);
        lsum = __fdividef(S, D);
    }

    // ---------------- block reduction ----------------
    #pragma unroll
    for (int off = 16; off; off >>= 1)
        lsum += __shfl_xor_sync(0xffffffffu, lsum, off);
    if ((tid & 31) == 0) wsum[tid >> 5] = lsum;
    __syncthreads();
    if (tid == 0) {
        float s = 0.f;
        #pragma unroll
        for (int w = 0; w < NTHREADS / 32; w++) s += wsum[w];
        g_blockSums[blockIdx.y * gridDim.x + blockIdx.x] = s;
        __threadfence();
        unsigned int prev = atomicAdd(&g_count, 1u);
        isLast = (prev == (unsigned int)(nBlocks - 1));
    }
    __syncthreads();

    // ---------------- last block: final deterministic reduce ----------------
    if (isLast) {
        double acc = 0.0;
        if ((nBlocks & 3) == 0) {
            const float4* p = (const float4*)g_blockSums;
            const int n4 = nBlocks >> 2;
            for (int i = tid; i < n4; i += NTHREADS) {
                float4 v = p[i];
                acc += (double)v.x + (double)v.y + (double)v.z + (double)v.w;
            }
        } else {
            for (int i = tid; i < nBlocks; i += NTHREADS)
                acc += (double)g_blockSums[i];
        }
        __shared__ double dsm[NTHREADS];
        dsm[tid] = acc;
        __syncthreads();
        #pragma unroll
        for (int s = NTHREADS / 2; s; s >>= 1) {
            if (tid < s) dsm[tid] += dsm[tid + s];
            __syncthreads();
        }
        if (tid == 0) {
            out[0] = (float)(dsm[0] * inv_n);
            g_count = 0;   // reset for next graph replay (deterministic)
        }
    }
}

extern "C" void kernel_launch(void* const* d_in, const int* in_sizes, int n_in,
                              void* d_out, int out_size)
{
    (void)n_in; (void)out_size;
    const float* img1 = (const float*)d_in[0];
    const float* img2 = (const float*)d_in[1];

    const long long n = (long long)in_sizes[0];
    int W = (int)(sqrt((double)n) + 0.5);
    if (W <= 0) W = 1;
    int H = (int)(n / W);

    dim3 grid((W + TILE - 1) / TILE, (H + TILE - 1) / TILE);
    const int nb = (int)(grid.x * grid.y);
    const double inv_n = 1.0 / ((double)H * (double)W);
    ssim_tile_kernel<<<grid, NTHREADS>>>(img1, img2, W, H, nb, inv_n,
                                         (float*)d_out);
}

// round 5
// speedup vs baseline: 1.5832x; 1.5832x over previous
#include <cuda_runtime.h>
#include <math.h>

#define TILE      32
#define HALO      5
#define RAW_W     (TILE + 2*HALO)   /* 42 */
#define RAWP      43                /* odd pitch -> conflict-free horizontal reads */
#define HALF_H    16                /* output rows per half */
#define HS_ROWS   (HALF_H + 2*HALO) /* 26 raw/hs rows per half */
#define HP        32                /* u64 hs pitch: vertical reads conflict-free */
#define HPX       33                /* f32 hs_xy pitch: conflict-free stores */
#define NTHREADS  256

typedef unsigned long long u64;

// Per-block partial sums (deterministic: each block writes exactly one slot).
__device__ float g_blockSums[65536];
__device__ unsigned int g_count = 0;

// Normalized 1D Gaussian, size 11, sigma 1.5 (matches cv2.getGaussianKernel).
__device__ __forceinline__ float gw(int t) {
    constexpr float G[11] = {
        0.00102838f, 0.00759876f, 0.03600077f, 0.10936069f, 0.21300553f,
        0.26601172f,
        0.21300553f, 0.10936069f, 0.03600077f, 0.00759876f, 0.00102838f };
    return G[t];
}
__device__ __forceinline__ int wux(int t) { return t <= 5 ? t : 10 - t; }

// packed duplicated weights in constant memory (keeps them out of registers)
__constant__ float2 cGW2[6] = {
    {0.00102838f, 0.00102838f}, {0.00759876f, 0.00759876f},
    {0.03600077f, 0.03600077f}, {0.10936069f, 0.10936069f},
    {0.21300553f, 0.21300553f}, {0.26601172f, 0.26601172f} };

__device__ __forceinline__ u64 ldw2(int t) {
    return *reinterpret_cast<const u64*>(&cGW2[wux(t)]);
}

// ---- packed f32x2 helpers (Blackwell) ----
__device__ __forceinline__ u64 pack2(float lo, float hi) {
    u64 r; asm("mov.b64 %0, {%1, %2};" : "=l"(r) : "f"(lo), "f"(hi)); return r;
}
__device__ __forceinline__ void unpack2(u64 v, float& lo, float& hi) {
    asm("mov.b64 {%0, %1}, %2;" : "=f"(lo), "=f"(hi) : "l"(v));
}
__device__ __forceinline__ u64 mul2(u64 a, u64 b) {
    u64 d; asm("mul.rn.f32x2 %0, %1, %2;" : "=l"(d) : "l"(a), "l"(b)); return d;
}
__device__ __forceinline__ u64 fma2(u64 a, u64 b, u64 c) {
    u64 d; asm("fma.rn.f32x2 %0, %1, %2, %3;" : "=l"(d) : "l"(a), "l"(b), "l"(c)); return d;
}

__global__ __launch_bounds__(NTHREADS, 6)
void ssim_tile_kernel(const float* __restrict__ img1,
                      const float* __restrict__ img2,
                      int W, int H, int nBlocks, double inv_n,
                      float* __restrict__ out)
{
    __shared__ float sx[HS_ROWS][RAWP];
    __shared__ float sy[HS_ROWS][RAWP];
    __shared__ u64   hs_mu[HS_ROWS][HP];    // packed (hblur(x),  hblur(y))
    __shared__ u64   hs_sq[HS_ROWS][HP];    // packed (hblur(xx), hblur(yy))
    __shared__ float hs_xy[HS_ROWS][HPX];   // hblur(xy)
    __shared__ float wsum[NTHREADS / 32];
    __shared__ bool  isLast;

    const int tid = threadIdx.x;
    const int bx = blockIdx.x * TILE;
    const int by = blockIdx.y * TILE;

    const float C1 = 6.5025f;    // (0.01*255)^2
    const float C2 = 58.5225f;   // (0.03*255)^2
    const float SCALE = 0.000244140625f;  // 2^-12: keep products in range

    float Sh[2], Dh[2];          // per-half rational partial sums

    #pragma unroll
    for (int h = 0; h < 2; h++) {
        // ---------- load raw rows [16h, 16h+26) with replicate padding ----------
        if (h) __syncthreads();   // raw overwrite must wait for half-0 hpass reads
        for (int i = tid; i < HS_ROWS * RAW_W; i += NTHREADS) {
            int r = i / RAW_W;
            int c = i - r * RAW_W;
            int gy = by - HALO + h * HALF_H + r; gy = gy < 0 ? 0 : (gy >= H ? H - 1 : gy);
            int gx = bx - HALO + c;              gx = gx < 0 ? 0 : (gx >= W ? W - 1 : gx);
            size_t idx = (size_t)gy * (size_t)W + (size_t)gx;
            sx[r][c] = img1[idx];
            sy[r][c] = img2[idx];
        }
        __syncthreads();

        // ---------- horizontal pass: 26 rows x 8 groups = 208 items (1 round) ----
        if (tid < HS_ROWS * 8) {
            const int r = tid >> 3;
            const int g = (tid & 7) << 2;

            u64   amu[4] = {0ull, 0ull, 0ull, 0ull};
            u64   asq[4] = {0ull, 0ull, 0ull, 0ull};
            float axy[4] = {0.f, 0.f, 0.f, 0.f};

            #pragma unroll
            for (int k = 0; k < 14; k++) {
                const float vx = sx[r][g + k];
                const float vy = sy[r][g + k];
                const u64   v2  = pack2(vx, vy);
                const u64   sq2 = mul2(v2, v2);
                const float xy  = vx * vy;
                #pragma unroll
                for (int o = 0; o < 4; o++) {
                    const int t = k - o;
                    if (t >= 0 && t < 11) {
                        const u64 w2 = ldw2(t);
                        amu[o] = fma2(v2,  w2, amu[o]);
                        asq[o] = fma2(sq2, w2, asq[o]);
                        axy[o] = fmaf(xy, gw(t), axy[o]);
                    }
                }
            }
            #pragma unroll
            for (int o = 0; o < 4; o++) {
                hs_mu[r][g + o] = amu[o];
                hs_sq[r][g + o] = asq[o];
                hs_xy[r][g + o] = axy[o];
            }
        }
        __syncthreads();

        // ---------- vertical pass + SSIM: 32 cols x 8 groups of 2 rows ----------
        {
            const int c  = tid & 31;
            const int r0 = (tid >> 5) * 2;   // local output rows r0, r0+1

            u64   vmu[2] = {0ull, 0ull};
            u64   vsq[2] = {0ull, 0ull};
            float vxy[2] = {0.f, 0.f};

            #pragma unroll
            for (int j = 0; j < 12; j++) {
                const u64   m = hs_mu[r0 + j][c];
                const u64   s = hs_sq[r0 + j][c];
                const float p = hs_xy[r0 + j][c];
                #pragma unroll
                for (int o = 0; o < 2; o++) {
                    const int t = j - o;
                    if (t >= 0 && t < 11) {
                        const u64 w2 = ldw2(t);
                        vmu[o] = fma2(m, w2, vmu[o]);
                        vsq[o] = fma2(s, w2, vsq[o]);
                        vxy[o] = fmaf(p, gw(t), vxy[o]);
                    }
                }
            }

            float nn[2], dd[2];
            #pragma unroll
            for (int o = 0; o < 2; o++) {
                const int gy = by + h * HALF_H + r0 + o;
                if (gy < H && bx + c < W) {
                    float mu1, mu2, exx, eyy;
                    unpack2(vmu[o], mu1, mu2);
                    unpack2(vsq[o], exx, eyy);
                    const float exy = vxy[o];
                    const float m11 = mu1 * mu1;
                    const float m22 = mu2 * mu2;
                    const float m12 = mu1 * mu2;
                    const float s1q = exx - m11;
                    const float s2q = eyy - m22;
                    const float s12 = exy - m12;
                    nn[o] = ((2.f * m12 + C1) * SCALE) * ((2.f * s12 + C2) * SCALE);
                    dd[o] = ((m11 + m22 + C1) * SCALE) * ((s1q + s2q + C2) * SCALE);
                } else {
                    nn[o] = 0.f;
                    dd[o] = 1.f;
                }
            }
            Sh[h] = fmaf(nn[0], dd[1], nn[1] * dd[0]);
            Dh[h] = dd[0] * dd[1];
        }
    }

    // combine both halves: one RCP per 4 pixels
    float lsum = __fdividef(fmaf(Sh[0], Dh[1], Sh[1] * Dh[0]), Dh[0] * Dh[1]);

    // ---------------- block reduction ----------------
    #pragma unroll
    for (int off = 16; off; off >>= 1)
        lsum += __shfl_xor_sync(0xffffffffu, lsum, off);
    if ((tid & 31) == 0) wsum[tid >> 5] = lsum;
    __syncthreads();
    if (tid == 0) {
        float s = 0.f;
        #pragma unroll
        for (int w = 0; w < NTHREADS / 32; w++) s += wsum[w];
        g_blockSums[blockIdx.y * gridDim.x + blockIdx.x] = s;
        __threadfence();
        unsigned int prev = atomicAdd(&g_count, 1u);
        isLast = (prev == (unsigned int)(nBlocks - 1));
    }
    __syncthreads();

    // ---------------- last block: final deterministic reduce ----------------
    if (isLast) {
        double acc = 0.0;
        if ((nBlocks & 3) == 0) {
            const float4* p = (const float4*)g_blockSums;
            const int n4 = nBlocks >> 2;
            for (int i = tid; i < n4; i += NTHREADS) {
                float4 v = p[i];
                acc += (double)v.x + (double)v.y + (double)v.z + (double)v.w;
            }
        } else {
            for (int i = tid; i < nBlocks; i += NTHREADS)
                acc += (double)g_blockSums[i];
        }
        __shared__ double dsm[NTHREADS];
        dsm[tid] = acc;
        __syncthreads();
        #pragma unroll
        for (int s = NTHREADS / 2; s; s >>= 1) {
            if (tid < s) dsm[tid] += dsm[tid + s];
            __syncthreads();
        }
        if (tid == 0) {
            out[0] = (float)(dsm[0] * inv_n);
            g_count = 0;   // reset for next graph replay (deterministic)
        }
    }
}

extern "C" void kernel_launch(void* const* d_in, const int* in_sizes, int n_in,
                              void* d_out, int out_size)
{
    (void)n_in; (void)out_size;
    const float* img1 = (const float*)d_in[0];
    const float* img2 = (const float*)d_in[1];

    const long long n = (long long)in_sizes[0];
    int W = (int)(sqrt((double)n) + 0.5);
    if (W <= 0) W = 1;
    int H = (int)(n / W);

    dim3 grid((W + TILE - 1) / TILE, (H + TILE - 1) / TILE);
    const int nb = (int)(grid.x * grid.y);
    const double inv_n = 1.0 / ((double)H * (double)W);
    ssim_tile_kernel<<<grid, NTHREADS>>>(img1, img2, W, H, nb, inv_n,
                                         (float*)d_out);
}

// round 6
// speedup vs baseline: 2.1667x; 1.3685x over previous
#include <cuda_runtime.h>
#include <math.h>

#define TILE      32
#define HALO      5
#define RAW       (TILE + 2*HALO)   /* 42 */
#define RAWP      43                /* odd u64 pitch -> staggered banks */
#define HP        33                /* odd u64 pitch for hs arrays */
#define NTHREADS  256

typedef unsigned long long u64;

// Per-block partial sums (deterministic: each block writes exactly one slot).
__device__ float g_blockSums[65536];
__device__ unsigned int g_count = 0;

// Normalized 1D Gaussian, size 11, sigma 1.5 (matches cv2.getGaussianKernel).
__device__ __forceinline__ float gw(int t) {
    constexpr float G[11] = {
        0.00102838f, 0.00759876f, 0.03600077f, 0.10936069f, 0.21300553f,
        0.26601172f,
        0.21300553f, 0.10936069f, 0.03600077f, 0.00759876f, 0.00102838f };
    return G[t];
}
__device__ __forceinline__ int wux(int t) { return t <= 5 ? t : 10 - t; }

// packed duplicated weights in constant memory (keeps them out of registers)
__constant__ float2 cGW2[6] = {
    {0.00102838f, 0.00102838f}, {0.00759876f, 0.00759876f},
    {0.03600077f, 0.03600077f}, {0.10936069f, 0.10936069f},
    {0.21300553f, 0.21300553f}, {0.26601172f, 0.26601172f} };

__device__ __forceinline__ u64 ldw2(int t) {
    return *reinterpret_cast<const u64*>(&cGW2[wux(t)]);
}

// ---- packed f32x2 helpers (Blackwell) ----
__device__ __forceinline__ u64 pack2(float lo, float hi) {
    u64 r; asm("mov.b64 %0, {%1, %2};" : "=l"(r) : "f"(lo), "f"(hi)); return r;
}
__device__ __forceinline__ void unpack2(u64 v, float& lo, float& hi) {
    asm("mov.b64 {%0, %1}, %2;" : "=f"(lo), "=f"(hi) : "l"(v));
}
__device__ __forceinline__ u64 fma2(u64 a, u64 b, u64 c) {
    u64 d; asm("fma.rn.f32x2 %0, %1, %2, %3;" : "=l"(d) : "l"(a), "l"(b), "l"(c)); return d;
}

__global__ __launch_bounds__(NTHREADS, 6)
void ssim_tile_kernel(const float* __restrict__ img1,
                      const float* __restrict__ img2,
                      int W, int H, int nBlocks, double inv_n,
                      float* __restrict__ out)
{
    __shared__ u64   raw[RAW][RAWP];    // packed (x, y)
    __shared__ u64   hs_mu[RAW][HP];    // packed (hblur(x), hblur(y))
    __shared__ u64   hs_sp[RAW][HP];    // packed (hblur(xx+yy), hblur(xy))
    __shared__ float wsum[NTHREADS / 32];
    __shared__ bool  isLast;

    const int tid = threadIdx.x;
    const int bx = blockIdx.x * TILE;
    const int by = blockIdx.y * TILE;

    // ---------------- load raw tile (packed) with replicate padding ----------------
    for (int i = tid; i < RAW * RAW; i += NTHREADS) {
        int r = i / RAW;
        int c = i - r * RAW;
        int gy = by - HALO + r; gy = gy < 0 ? 0 : (gy >= H ? H - 1 : gy);
        int gx = bx - HALO + c; gx = gx < 0 ? 0 : (gx >= W ? W - 1 : gx);
        size_t idx = (size_t)gy * (size_t)W + (size_t)gx;
        raw[r][c] = pack2(img1[idx], img2[idx]);
    }
    __syncthreads();

    // ---------------- horizontal pass: 42 rows x 8 groups of 4 output cols ----------
    for (int i = tid; i < RAW * 8; i += NTHREADS) {
        const int r = i >> 3;
        const int g = (i & 7) << 2;

        u64 amu[4] = {0ull, 0ull, 0ull, 0ull};
        u64 asp[4] = {0ull, 0ull, 0ull, 0ull};

        #pragma unroll
        for (int k = 0; k < 14; k++) {
            const u64 v2 = raw[r][g + k];
            float vx, vy;
            unpack2(v2, vx, vy);
            const float ss = fmaf(vx, vx, vy * vy);   // x^2 + y^2
            const float xy = vx * vy;
            const u64 p2 = pack2(ss, xy);
            #pragma unroll
            for (int o = 0; o < 4; o++) {
                const int t = k - o;
                if (t >= 0 && t < 11) {
                    const u64 w2 = ldw2(t);
                    amu[o] = fma2(v2, w2, amu[o]);
                    asp[o] = fma2(p2, w2, asp[o]);
                }
            }
        }
        #pragma unroll
        for (int o = 0; o < 4; o++) {
            hs_mu[r][g + o] = amu[o];
            hs_sp[r][g + o] = asp[o];
        }
    }
    __syncthreads();

    // ---------------- vertical pass + SSIM: 32 cols x 8 row-groups of 4 rows --------
    float lsum = 0.f;
    {
        const int c  = tid & 31;
        const int r0 = (tid >> 5) * 4;   // output rows r0..r0+3

        u64 vmu[4] = {0ull, 0ull, 0ull, 0ull};
        u64 vsp[4] = {0ull, 0ull, 0ull, 0ull};

        #pragma unroll
        for (int j = 0; j < 14; j++) {
            const u64 m = hs_mu[r0 + j][c];
            const u64 s = hs_sp[r0 + j][c];
            #pragma unroll
            for (int o = 0; o < 4; o++) {
                const int t = j - o;
                if (t >= 0 && t < 11) {
                    const u64 w2 = ldw2(t);
                    vmu[o] = fma2(m, w2, vmu[o]);
                    vsp[o] = fma2(s, w2, vsp[o]);
                }
            }
        }

        const float C1 = 6.5025f;    // (0.01*255)^2
        const float C2 = 58.5225f;   // (0.03*255)^2
        const float SCALE = 0.000244140625f;  // 2^-12: keep 4-products in range

        float nn[4], dd[4];
        #pragma unroll
        for (int o = 0; o < 4; o++) {
            if (by + r0 + o < H && bx + c < W) {
                float mu1, mu2, sqs, exy;
                unpack2(vmu[o], mu1, mu2);
                unpack2(vsp[o], sqs, exy);   // sqs = G(xx)+G(yy), exy = G(xy)
                const float m11  = mu1 * mu1;
                const float m22  = mu2 * mu2;
                const float m12  = mu1 * mu2;
                const float msum = m11 + m22;
                const float s12  = exy - m12;
                const float ssum = sqs - msum;        // sigma1^2 + sigma2^2
                nn[o] = ((2.f * m12 + C1) * SCALE) * ((2.f * s12 + C2) * SCALE);
                dd[o] = ((msum + C1) * SCALE) * ((ssum + C2) * SCALE);
            } else {
                nn[o] = 0.f;
                dd[o] = 1.f;
            }
        }
        // sum_i n_i/d_i = (sum_i n_i * prod_{j!=i} d_j) / prod_j d_j -> one RCP / 4 px
        const float d01 = dd[0] * dd[1];
        const float d23 = dd[2] * dd[3];
        const float D   = d01 * d23;
        const float s01 = fmaf(nn[0], dd[1], nn[1] * dd[0]);
        const float s23 = fmaf(nn[2], dd[3], nn[3] * dd[2]);
        const float S   = fmaf(s01, d23, s23 * d01);
        lsum = __fdividef(S, D);
    }

    // ---------------- block reduction ----------------
    #pragma unroll
    for (int off = 16; off; off >>= 1)
        lsum += __shfl_xor_sync(0xffffffffu, lsum, off);
    if ((tid & 31) == 0) wsum[tid >> 5] = lsum;
    __syncthreads();
    if (tid == 0) {
        float s = 0.f;
        #pragma unroll
        for (int w = 0; w < NTHREADS / 32; w++) s += wsum[w];
        g_blockSums[blockIdx.y * gridDim.x + blockIdx.x] = s;
        __threadfence();
        unsigned int prev = atomicAdd(&g_count, 1u);
        isLast = (prev == (unsigned int)(nBlocks - 1));
    }
    __syncthreads();

    // ---------------- last block: final deterministic reduce ----------------
    if (isLast) {
        // reuse hs_mu storage for the double scratch (all hs uses are done)
        double* dsm = reinterpret_cast<double*>(&hs_mu[0][0]);
        double acc = 0.0;
        if ((nBlocks & 3) == 0) {
            const float4* p = (const float4*)g_blockSums;
            const int n4 = nBlocks >> 2;
            for (int i = tid; i < n4; i += NTHREADS) {
                float4 v = p[i];
                acc += (double)v.x + (double)v.y + (double)v.z + (double)v.w;
            }
        } else {
            for (int i = tid; i < nBlocks; i += NTHREADS)
                acc += (double)g_blockSums[i];
        }
        dsm[tid] = acc;
        __syncthreads();
        #pragma unroll
        for (int s = NTHREADS / 2; s; s >>= 1) {
            if (tid < s) dsm[tid] += dsm[tid + s];
            __syncthreads();
        }
        if (tid == 0) {
            out[0] = (float)(dsm[0] * inv_n);
            g_count = 0;   // reset for next graph replay (deterministic)
        }
    }
}

extern "C" void kernel_launch(void* const* d_in, const int* in_sizes, int n_in,
                              void* d_out, int out_size)
{
    (void)n_in; (void)out_size;
    const float* img1 = (const float*)d_in[0];
    const float* img2 = (const float*)d_in[1];

    const long long n = (long long)in_sizes[0];
    int W = (int)(sqrt((double)n) + 0.5);
    if (W <= 0) W = 1;
    int H = (int)(n / W);

    dim3 grid((W + TILE - 1) / TILE, (H + TILE - 1) / TILE);
    const int nb = (int)(grid.x * grid.y);
    const double inv_n = 1.0 / ((double)H * (double)W);
    ssim_tile_kernel<<<grid, NTHREADS>>>(img1, img2, W, H, nb, inv_n,
                                         (float*)d_out);
}

// round 7
// speedup vs baseline: 2.1946x; 1.0129x over previous
#include <cuda_runtime.h>
#include <math.h>

#define TILE      32
#define HALO      5
#define RAW       (TILE + 2*HALO)   /* 42 */
#define RAWP      43                /* odd u64 pitch -> staggered banks */
#define HP        33                /* hs pitch in (u64,u64) pairs */
#define NTHREADS  256

typedef unsigned long long u64;

// Per-block partial sums (deterministic: each block writes exactly one slot).
__device__ float g_blockSums[65536];
__device__ unsigned int g_count = 0;

// Normalized 1D Gaussian, size 11, sigma 1.5 (matches cv2.getGaussianKernel).
__device__ __forceinline__ float gw(int t) {
    constexpr float G[11] = {
        0.00102838f, 0.00759876f, 0.03600077f, 0.10936069f, 0.21300553f,
        0.26601172f,
        0.21300553f, 0.10936069f, 0.03600077f, 0.00759876f, 0.00102838f };
    return G[t];
}
__device__ __forceinline__ int wux(int t) { return t <= 5 ? t : 10 - t; }

// packed duplicated weights in constant memory (keeps them out of registers)
__constant__ float2 cGW2[6] = {
    {0.00102838f, 0.00102838f}, {0.00759876f, 0.00759876f},
    {0.03600077f, 0.03600077f}, {0.10936069f, 0.10936069f},
    {0.21300553f, 0.21300553f}, {0.26601172f, 0.26601172f} };

__device__ __forceinline__ u64 ldw2(int t) {
    return *reinterpret_cast<const u64*>(&cGW2[wux(t)]);
}

// ---- packed f32x2 helpers (Blackwell) ----
__device__ __forceinline__ u64 pack2(float lo, float hi) {
    u64 r; asm("mov.b64 %0, {%1, %2};" : "=l"(r) : "f"(lo), "f"(hi)); return r;
}
__device__ __forceinline__ void unpack2(u64 v, float& lo, float& hi) {
    asm("mov.b64 {%0, %1}, %2;" : "=f"(lo), "=f"(hi) : "l"(v));
}
__device__ __forceinline__ u64 fma2(u64 a, u64 b, u64 c) {
    u64 d; asm("fma.rn.f32x2 %0, %1, %2, %3;" : "=l"(d) : "l"(a), "l"(b), "l"(c)); return d;
}

__global__ __launch_bounds__(NTHREADS, 6)
void ssim_tile_kernel(const float* __restrict__ img1,
                      const float* __restrict__ img2,
                      int W, int H, int nBlocks, double inv_n,
                      float* __restrict__ out)
{
    __shared__ u64   raw[RAW][RAWP];       // packed (x, y)
    __shared__ u64   hs[RAW][HP][2];       // [0]=(G(x),G(y))  [1]=(G(xx+yy),G(xy))
    __shared__ float wsum[NTHREADS / 32];
    __shared__ bool  isLast;

    const int tid = threadIdx.x;
    const int bx = blockIdx.x * TILE;
    const int by = blockIdx.y * TILE;

    // ---------------- load raw tile (packed) with replicate padding ----------------
    // 1764 items over 256 threads: stride stepping, no division.
    {
        int r = tid / RAW;              // one division total (constant divisor)
        int c = tid - r * RAW;
        const bool interior = (bx >= HALO) && (by >= HALO) &&
                              (bx + TILE + HALO <= W) && (by + TILE + HALO <= H);
        if (interior) {
            const float* __restrict__ p1 =
                img1 + (size_t)(by - HALO) * (size_t)W + (bx - HALO);
            const float* __restrict__ p2 =
                img2 + (size_t)(by - HALO) * (size_t)W + (bx - HALO);
            #pragma unroll
            for (int it = 0; it < 7; it++) {
                if (it < 6 || r < RAW) {
                    size_t idx = (size_t)r * (size_t)W + (size_t)c;
                    raw[r][c] = pack2(p1[idx], p2[idx]);
                }
                r += 6; c += 4;                 // 256 = 6*42 + 4
                if (c >= RAW) { c -= RAW; r += 1; }
            }
        } else {
            #pragma unroll
            for (int it = 0; it < 7; it++) {
                if (it < 6 || r < RAW) {
                    int gy = by - HALO + r; gy = gy < 0 ? 0 : (gy >= H ? H - 1 : gy);
                    int gx = bx - HALO + c; gx = gx < 0 ? 0 : (gx >= W ? W - 1 : gx);
                    size_t idx = (size_t)gy * (size_t)W + (size_t)gx;
                    raw[r][c] = pack2(img1[idx], img2[idx]);
                }
                r += 6; c += 4;
                if (c >= RAW) { c -= RAW; r += 1; }
            }
        }
    }
    __syncthreads();

    // ---------------- horizontal pass: 42 rows x 8 groups of 4 output cols ----------
    for (int i = tid; i < RAW * 8; i += NTHREADS) {
        const int r = i >> 3;
        const int g = (i & 7) << 2;

        u64 amu[4] = {0ull, 0ull, 0ull, 0ull};
        u64 asp[4] = {0ull, 0ull, 0ull, 0ull};

        #pragma unroll
        for (int k = 0; k < 14; k++) {
            const u64 v2 = raw[r][g + k];
            float vx, vy;
            unpack2(v2, vx, vy);
            const float ss = fmaf(vx, vx, vy * vy);   // x^2 + y^2
            const float xy = vx * vy;
            const u64 p2 = pack2(ss, xy);
            #pragma unroll
            for (int o = 0; o < 4; o++) {
                const int t = k - o;
                if (t >= 0 && t < 11) {
                    const u64 w2 = ldw2(t);
                    amu[o] = fma2(v2, w2, amu[o]);
                    asp[o] = fma2(p2, w2, asp[o]);
                }
            }
        }
        #pragma unroll
        for (int o = 0; o < 4; o++) {
            ulonglong2* dst = reinterpret_cast<ulonglong2*>(&hs[r][g + o][0]);
            *dst = make_ulonglong2(amu[o], asp[o]);    // STS.128
        }
    }
    __syncthreads();

    // ---------------- vertical pass + SSIM: 32 cols x 8 row-groups of 4 rows --------
    float lsum = 0.f;
    {
        const int c  = tid & 31;
        const int r0 = (tid >> 5) * 4;   // output rows r0..r0+3

        u64 vmu[4] = {0ull, 0ull, 0ull, 0ull};
        u64 vsp[4] = {0ull, 0ull, 0ull, 0ull};

        #pragma unroll
        for (int j = 0; j < 14; j++) {
            const ulonglong2 v =
                *reinterpret_cast<const ulonglong2*>(&hs[r0 + j][c][0]);  // LDS.128
            const u64 m = v.x;
            const u64 s = v.y;
            #pragma unroll
            for (int o = 0; o < 4; o++) {
                const int t = j - o;
                if (t >= 0 && t < 11) {
                    const u64 w2 = ldw2(t);
                    vmu[o] = fma2(m, w2, vmu[o]);
                    vsp[o] = fma2(s, w2, vsp[o]);
                }
            }
        }

        const float C1 = 6.5025f;    // (0.01*255)^2
        const float C2 = 58.5225f;   // (0.03*255)^2
        const float SCALE = 0.000244140625f;  // 2^-12: keep 4-products in range

        float nn[4], dd[4];
        #pragma unroll
        for (int o = 0; o < 4; o++) {
            if (by + r0 + o < H && bx + c < W) {
                float mu1, mu2, sqs, exy;
                unpack2(vmu[o], mu1, mu2);
                unpack2(vsp[o], sqs, exy);   // sqs = G(xx)+G(yy), exy = G(xy)
                const float m11  = mu1 * mu1;
                const float m22  = mu2 * mu2;
                const float m12  = mu1 * mu2;
                const float msum = m11 + m22;
                const float s12  = exy - m12;
                const float ssum = sqs - msum;        // sigma1^2 + sigma2^2
                nn[o] = ((2.f * m12 + C1) * SCALE) * ((2.f * s12 + C2) * SCALE);
                dd[o] = ((msum + C1) * SCALE) * ((ssum + C2) * SCALE);
            } else {
                nn[o] = 0.f;
                dd[o] = 1.f;
            }
        }
        // sum_i n_i/d_i = (sum_i n_i * prod_{j!=i} d_j) / prod_j d_j -> one RCP / 4 px
        const float d01 = dd[0] * dd[1];
        const float d23 = dd[2] * dd[3];
        const float D   = d01 * d23;
        const float s01 = fmaf(nn[0], dd[1], nn[1] * dd[0]);
        const float s23 = fmaf(nn[2], dd[3], nn[3] * dd[2]);
        const float S   = fmaf(s01, d23, s23 * d01);
        lsum = __fdividef(S, D);
    }

    // ---------------- block reduction ----------------
    #pragma unroll
    for (int off = 16; off; off >>= 1)
        lsum += __shfl_xor_sync(0xffffffffu, lsum, off);
    if ((tid & 31) == 0) wsum[tid >> 5] = lsum;
    __syncthreads();
    if (tid == 0) {
        float s = 0.f;
        #pragma unroll
        for (int w = 0; w < NTHREADS / 32; w++) s += wsum[w];
        g_blockSums[blockIdx.y * gridDim.x + blockIdx.x] = s;
        __threadfence();
        unsigned int prev = atomicAdd(&g_count, 1u);
        isLast = (prev == (unsigned int)(nBlocks - 1));
    }
    __syncthreads();

    // ---------------- last block: final deterministic reduce ----------------
    if (isLast) {
        // reuse raw storage for the double scratch (all raw uses are done)
        double* dsm = reinterpret_cast<double*>(&raw[0][0]);
        double acc = 0.0;
        if ((nBlocks & 3) == 0) {
            const float4* p = (const float4*)g_blockSums;
            const int n4 = nBlocks >> 2;
            for (int i = tid; i < n4; i += NTHREADS) {
                float4 v = p[i];
                acc += (double)v.x + (double)v.y + (double)v.z + (double)v.w;
            }
        } else {
            for (int i = tid; i < nBlocks; i += NTHREADS)
                acc += (double)g_blockSums[i];
        }
        dsm[tid] = acc;
        __syncthreads();
        #pragma unroll
        for (int s = NTHREADS / 2; s; s >>= 1) {
            if (tid < s) dsm[tid] += dsm[tid + s];
            __syncthreads();
        }
        if (tid == 0) {
            out[0] = (float)(dsm[0] * inv_n);
            g_count = 0;   // reset for next graph replay (deterministic)
        }
    }
}

extern "C" void kernel_launch(void* const* d_in, const int* in_sizes, int n_in,
                              void* d_out, int out_size)
{
    (void)n_in; (void)out_size;
    const float* img1 = (const float*)d_in[0];
    const float* img2 = (const float*)d_in[1];

    const long long n = (long long)in_sizes[0];
    int W = (int)(sqrt((double)n) + 0.5);
    if (W <= 0) W = 1;
    int H = (int)(n / W);

    dim3 grid((W + TILE - 1) / TILE, (H + TILE - 1) / TILE);
    const int nb = (int)(grid.x * grid.y);
    const double inv_n = 1.0 / ((double)H * (double)W);
    ssim_tile_kernel<<<grid, NTHREADS>>>(img1, img2, W, H, nb, inv_n,
                                         (float*)d_out);
}

// round 8
// speedup vs baseline: 2.8819x; 1.3132x over previous
#include <cuda_runtime.h>
#include <math.h>

#define TILE      32
#define HALO      5
#define RAW       (TILE + 2*HALO)   /* 42 columns incl. halo */
#define VP        43                /* vs pitch in 16B pairs (odd -> bank stagger) */
#define NTHREADS  256

typedef unsigned long long u64;

// Per-block partial sums (deterministic: each block writes exactly one slot).
__device__ float g_blockSums[65536];
__device__ unsigned int g_count = 0;

// Normalized 1D Gaussian, size 11, sigma 1.5 (matches cv2.getGaussianKernel).
__device__ __forceinline__ float gw(int t) {
    constexpr float G[11] = {
        0.00102838f, 0.00759876f, 0.03600077f, 0.10936069f, 0.21300553f,
        0.26601172f,
        0.21300553f, 0.10936069f, 0.03600077f, 0.00759876f, 0.00102838f };
    return G[t];
}
__device__ __forceinline__ int wux(int t) { return t <= 5 ? t : 10 - t; }

// packed duplicated weights in constant memory (keeps them out of registers)
__constant__ float2 cGW2[6] = {
    {0.00102838f, 0.00102838f}, {0.00759876f, 0.00759876f},
    {0.03600077f, 0.03600077f}, {0.10936069f, 0.10936069f},
    {0.21300553f, 0.21300553f}, {0.26601172f, 0.26601172f} };

__device__ __forceinline__ u64 ldw2(int t) {
    return *reinterpret_cast<const u64*>(&cGW2[wux(t)]);
}

// ---- packed f32x2 helpers (Blackwell) ----
__device__ __forceinline__ u64 pack2(float lo, float hi) {
    u64 r; asm("mov.b64 %0, {%1, %2};" : "=l"(r) : "f"(lo), "f"(hi)); return r;
}
__device__ __forceinline__ void unpack2(u64 v, float& lo, float& hi) {
    asm("mov.b64 {%0, %1}, %2;" : "=f"(lo), "=f"(hi) : "l"(v));
}
__device__ __forceinline__ u64 fma2(u64 a, u64 b, u64 c) {
    u64 d; asm("fma.rn.f32x2 %0, %1, %2, %3;" : "=l"(d) : "l"(a), "l"(b), "l"(c)); return d;
}

// Vertical 11-tap blur for one (column, 4-row-group) item, reading gmem directly.
// Writes packed ((G(x),G(y)),(G(xx+yy),G(xy))) into vs.
template<bool CLAMP>
__device__ __forceinline__ void vitem(const float* __restrict__ img1,
                                      const float* __restrict__ img2,
                                      int W, int H, int bx, int by, int item,
                                      u64 (*vs)[VP][2])
{
    const int grp = item / RAW;          // const-divisor -> mul/shift
    const int col = item - grp * RAW;
    const int r0  = grp * 4;             // output rows r0..r0+3 (tile-local)

    u64 vmu[4] = {0ull, 0ull, 0ull, 0ull};
    u64 vsp[4] = {0ull, 0ull, 0ull, 0ull};

    int gx = bx - HALO + col;
    if (CLAMP) gx = min(max(gx, 0), W - 1);

    const float* __restrict__ p1;
    const float* __restrict__ p2;
    if (!CLAMP) {
        const size_t base = (size_t)(by + r0 - HALO) * (size_t)W + (size_t)gx;
        p1 = img1 + base;
        p2 = img2 + base;
    }

    #pragma unroll
    for (int j = 0; j < 14; j++) {
        float x, y;
        if (CLAMP) {
            int gy = by + r0 - HALO + j;
            gy = min(max(gy, 0), H - 1);
            const size_t idx = (size_t)gy * (size_t)W + (size_t)gx;
            x = __ldg(img1 + idx);
            y = __ldg(img2 + idx);
        } else {
            x = __ldg(p1);
            y = __ldg(p2);
            p1 += W;
            p2 += W;
        }
        const u64 v2 = pack2(x, y);
        const float ss = fmaf(x, x, y * y);    // x^2 + y^2
        const float xy = x * y;
        const u64 p2v = pack2(ss, xy);
        #pragma unroll
        for (int o = 0; o < 4; o++) {
            const int t = j - o;
            if (t >= 0 && t < 11) {
                const u64 w2 = ldw2(t);
                vmu[o] = fma2(v2,  w2, vmu[o]);
                vsp[o] = fma2(p2v, w2, vsp[o]);
            }
        }
    }
    #pragma unroll
    for (int o = 0; o < 4; o++) {
        ulonglong2* dst = reinterpret_cast<ulonglong2*>(&vs[r0 + o][col][0]);
        *dst = make_ulonglong2(vmu[o], vsp[o]);    // STS.128
    }
}

__global__ __launch_bounds__(NTHREADS, 6)
void ssim_tile_kernel(const float* __restrict__ img1,
                      const float* __restrict__ img2,
                      int W, int H, int nBlocks, double inv_n,
                      float* __restrict__ out)
{
    __shared__ u64   vs[TILE][VP][2];   // vertical-blurred, packed 16B/px
    __shared__ float wsum[NTHREADS / 32];
    __shared__ bool  isLast;

    const int tid = threadIdx.x;
    const int bx = blockIdx.x * TILE;
    const int by = blockIdx.y * TILE;

    // ---------------- vertical pass from gmem: 42 cols x 8 row-groups = 336 items ----
    const bool interior = (bx >= HALO) && (by >= HALO) &&
                          (bx + TILE + HALO <= W) && (by + TILE + HALO <= H);
    if (interior) {
        vitem<false>(img1, img2, W, H, bx, by, tid, vs);
        if (tid < RAW * 8 - NTHREADS)
            vitem<false>(img1, img2, W, H, bx, by, tid + NTHREADS, vs);
    } else {
        vitem<true>(img1, img2, W, H, bx, by, tid, vs);
        if (tid < RAW * 8 - NTHREADS)
            vitem<true>(img1, img2, W, H, bx, by, tid + NTHREADS, vs);
    }
    __syncthreads();

    // ---------------- horizontal pass + SSIM: 32 rows x 8 groups of 4 cols ----------
    // Lane map: r=(tid>>5)*4+(tid&3), g=(tid>>2)&7 -> each 8-lane LDS.128 phase
    // covers 4 rows x 2 groups = 8 distinct banks (pitch 43 pairs).
    float lsum = 0.f;
    {
        const int r  = ((tid >> 5) << 2) | (tid & 3);
        const int g4 = ((tid >> 2) & 7) << 2;   // output cols g4..g4+3

        u64 hmu[4] = {0ull, 0ull, 0ull, 0ull};
        u64 hsp[4] = {0ull, 0ull, 0ull, 0ull};

        #pragma unroll
        for (int k = 0; k < 14; k++) {
            const ulonglong2 v =
                *reinterpret_cast<const ulonglong2*>(&vs[r][g4 + k][0]);  // LDS.128
            const u64 m = v.x;
            const u64 s = v.y;
            #pragma unroll
            for (int o = 0; o < 4; o++) {
                const int t = k - o;
                if (t >= 0 && t < 11) {
                    const u64 w2 = ldw2(t);
                    hmu[o] = fma2(m, w2, hmu[o]);
                    hsp[o] = fma2(s, w2, hsp[o]);
                }
            }
        }

        const float C1 = 6.5025f;    // (0.01*255)^2
        const float C2 = 58.5225f;   // (0.03*255)^2
        const float SCALE = 0.000244140625f;  // 2^-12: keep 4-products in range

        float nn[4], dd[4];
        #pragma unroll
        for (int o = 0; o < 4; o++) {
            if (by + r < H && bx + g4 + o < W) {
                float mu1, mu2, sqs, exy;
                unpack2(hmu[o], mu1, mu2);
                unpack2(hsp[o], sqs, exy);   // sqs = G(xx)+G(yy), exy = G(xy)
                const float m11  = mu1 * mu1;
                const float m22  = mu2 * mu2;
                const float m12  = mu1 * mu2;
                const float msum = m11 + m22;
                const float s12  = exy - m12;
                const float ssum = sqs - msum;        // sigma1^2 + sigma2^2
                nn[o] = ((2.f * m12 + C1) * SCALE) * ((2.f * s12 + C2) * SCALE);
                dd[o] = ((msum + C1) * SCALE) * ((ssum + C2) * SCALE);
            } else {
                nn[o] = 0.f;
                dd[o] = 1.f;
            }
        }
        // sum_i n_i/d_i = (sum_i n_i * prod_{j!=i} d_j) / prod_j d_j -> one RCP / 4 px
        const float d01 = dd[0] * dd[1];
        const float d23 = dd[2] * dd[3];
        const float D   = d01 * d23;
        const float s01 = fmaf(nn[0], dd[1], nn[1] * dd[0]);
        const float s23 = fmaf(nn[2], dd[3], nn[3] * dd[2]);
        const float S   = fmaf(s01, d23, s23 * d01);
        lsum = __fdividef(S, D);
    }

    // ---------------- block reduction ----------------
    #pragma unroll
    for (int off = 16; off; off >>= 1)
        lsum += __shfl_xor_sync(0xffffffffu, lsum, off);
    if ((tid & 31) == 0) wsum[tid >> 5] = lsum;
    __syncthreads();
    if (tid == 0) {
        float s = 0.f;
        #pragma unroll
        for (int w = 0; w < NTHREADS / 32; w++) s += wsum[w];
        g_blockSums[blockIdx.y * gridDim.x + blockIdx.x] = s;
        __threadfence();
        unsigned int prev = atomicAdd(&g_count, 1u);
        isLast = (prev == (unsigned int)(nBlocks - 1));
    }
    __syncthreads();

    // ---------------- last block: final deterministic reduce ----------------
    if (isLast) {
        // reuse vs storage for the double scratch (all vs uses are done)
        double* dsm = reinterpret_cast<double*>(&vs[0][0][0]);
        double acc = 0.0;
        if ((nBlocks & 3) == 0) {
            const float4* p = (const float4*)g_blockSums;
            const int n4 = nBlocks >> 2;
            for (int i = tid; i < n4; i += NTHREADS) {
                float4 v = p[i];
                acc += (double)v.x + (double)v.y + (double)v.z + (double)v.w;
            }
        } else {
            for (int i = tid; i < nBlocks; i += NTHREADS)
                acc += (double)g_blockSums[i];
        }
        dsm[tid] = acc;
        __syncthreads();
        #pragma unroll
        for (int s = NTHREADS / 2; s; s >>= 1) {
            if (tid < s) dsm[tid] += dsm[tid + s];
            __syncthreads();
        }
        if (tid == 0) {
            out[0] = (float)(dsm[0] * inv_n);
            g_count = 0;   // reset for next graph replay (deterministic)
        }
    }
}

extern "C" void kernel_launch(void* const* d_in, const int* in_sizes, int n_in,
                              void* d_out, int out_size)
{
    (void)n_in; (void)out_size;
    const float* img1 = (const float*)d_in[0];
    const float* img2 = (const float*)d_in[1];

    const long long n = (long long)in_sizes[0];
    int W = (int)(sqrt((double)n) + 0.5);
    if (W <= 0) W = 1;
    int H = (int)(n / W);

    dim3 grid((W + TILE - 1) / TILE, (H + TILE - 1) / TILE);
    const int nb = (int)(grid.x * grid.y);
    const double inv_n = 1.0 / ((double)H * (double)W);
    ssim_tile_kernel<<<grid, NTHREADS>>>(img1, img2, W, H, nb, inv_n,
                                         (float*)d_out);
}

// round 9
// speedup vs baseline: 3.1441x; 1.0910x over previous
#include <cuda_runtime.h>
#include <math.h>

#define TILE_W    112
#define TILE_H    8
#define HALO      5
#define RAW_W     (TILE_W + 2*HALO)   /* 122 columns incl. halo */
#define VP        123                 /* vs pitch in 16B pairs (mod 8 = 3, odd) */
#define NTHREADS  256
#define NGROUPS   (TILE_H / 4)        /* 2 row groups of 4 */
#define VITEMS    (RAW_W * NGROUPS)   /* 244 */
#define HITEMS    (TILE_H * (TILE_W/4)) /* 224 */

typedef unsigned long long u64;

// Per-block partial sums (deterministic: each block writes exactly one slot).
__device__ float g_blockSums[65536];
__device__ unsigned int g_count = 0;

// Normalized 1D Gaussian, size 11, sigma 1.5 (matches cv2.getGaussianKernel).
__device__ __forceinline__ float gw(int t) {
    constexpr float G[11] = {
        0.00102838f, 0.00759876f, 0.03600077f, 0.10936069f, 0.21300553f,
        0.26601172f,
        0.21300553f, 0.10936069f, 0.03600077f, 0.00759876f, 0.00102838f };
    return G[t];
}
__device__ __forceinline__ int wux(int t) { return t <= 5 ? t : 10 - t; }

// packed duplicated weights in constant memory (keeps them out of registers)
__constant__ float2 cGW2[6] = {
    {0.00102838f, 0.00102838f}, {0.00759876f, 0.00759876f},
    {0.03600077f, 0.03600077f}, {0.10936069f, 0.10936069f},
    {0.21300553f, 0.21300553f}, {0.26601172f, 0.26601172f} };

__device__ __forceinline__ u64 ldw2(int t) {
    return *reinterpret_cast<const u64*>(&cGW2[wux(t)]);
}

// ---- packed f32x2 helpers (Blackwell) ----
__device__ __forceinline__ u64 pack2(float lo, float hi) {
    u64 r; asm("mov.b64 %0, {%1, %2};" : "=l"(r) : "f"(lo), "f"(hi)); return r;
}
__device__ __forceinline__ void unpack2(u64 v, float& lo, float& hi) {
    asm("mov.b64 {%0, %1}, %2;" : "=f"(lo), "=f"(hi) : "l"(v));
}
__device__ __forceinline__ u64 fma2(u64 a, u64 b, u64 c) {
    u64 d; asm("fma.rn.f32x2 %0, %1, %2, %3;" : "=l"(d) : "l"(a), "l"(b), "l"(c)); return d;
}

// Vertical 11-tap blur for one (column, 4-row-group) item, reading gmem directly.
// Writes packed ((G(x),G(y)),(G(xx+yy),G(xy))) into vs.
template<bool CLAMP>
__device__ __forceinline__ void vitem(const float* __restrict__ img1,
                                      const float* __restrict__ img2,
                                      int W, int H, int bx, int by, int item,
                                      u64 (*vs)[VP][2])
{
    const int grp = (item >= RAW_W) ? 1 : 0;
    const int col = item - grp * RAW_W;
    const int r0  = grp * 4;             // output rows r0..r0+3 (tile-local)

    u64 vmu[4] = {0ull, 0ull, 0ull, 0ull};
    u64 vsp[4] = {0ull, 0ull, 0ull, 0ull};

    int gx = bx - HALO + col;
    if (CLAMP) gx = min(max(gx, 0), W - 1);

    const float* __restrict__ p1;
    const float* __restrict__ p2;
    if (!CLAMP) {
        const size_t base = (size_t)(by + r0 - HALO) * (size_t)W + (size_t)gx;
        p1 = img1 + base;
        p2 = img2 + base;
    }

    #pragma unroll
    for (int j = 0; j < 14; j++) {
        float x, y;
        if (CLAMP) {
            int gy = by + r0 - HALO + j;
            gy = min(max(gy, 0), H - 1);
            const size_t idx = (size_t)gy * (size_t)W + (size_t)gx;
            x = __ldg(img1 + idx);
            y = __ldg(img2 + idx);
        } else {
            x = __ldg(p1);
            y = __ldg(p2);
            p1 += W;
            p2 += W;
        }
        const u64 v2 = pack2(x, y);
        const float ss = fmaf(x, x, y * y);    // x^2 + y^2
        const float xy = x * y;
        const u64 p2v = pack2(ss, xy);
        #pragma unroll
        for (int o = 0; o < 4; o++) {
            const int t = j - o;
            if (t >= 0 && t < 11) {
                const u64 w2 = ldw2(t);
                vmu[o] = fma2(v2,  w2, vmu[o]);
                vsp[o] = fma2(p2v, w2, vsp[o]);
            }
        }
    }
    #pragma unroll
    for (int o = 0; o < 4; o++) {
        ulonglong2* dst = reinterpret_cast<ulonglong2*>(&vs[r0 + o][col][0]);
        *dst = make_ulonglong2(vmu[o], vsp[o]);    // STS.128
    }
}

__global__ __launch_bounds__(NTHREADS, 6)
void ssim_tile_kernel(const float* __restrict__ img1,
                      const float* __restrict__ img2,
                      int W, int H, int nBlocks, double inv_n,
                      float* __restrict__ out)
{
    __shared__ u64   vs[TILE_H][VP][2];   // vertical-blurred, packed 16B/px
    __shared__ float wsum[NTHREADS / 32];
    __shared__ bool  isLast;

    const int tid = threadIdx.x;
    const int bx = blockIdx.x * TILE_W;
    const int by = blockIdx.y * TILE_H;

    // ---------------- vertical pass from gmem: 122 cols x 2 row-groups = 244 items ----
    const bool interior = (bx >= HALO) && (by >= HALO) &&
                          (bx + TILE_W + HALO <= W) && (by + TILE_H + HALO <= H);
    if (tid < VITEMS) {
        if (interior) vitem<false>(img1, img2, W, H, bx, by, tid, vs);
        else          vitem<true >(img1, img2, W, H, bx, by, tid, vs);
    }
    __syncthreads();

    // ---------------- horizontal pass + SSIM: 8 rows x 28 groups of 4 cols ----------
    // Lane map: r=tid&7 (pitch 123, 123*r mod 8 distinct) -> conflict-free LDS.128.
    float lsum = 0.f;
    if (tid < HITEMS) {
        const int r  = tid & 7;
        const int g4 = (tid >> 3) << 2;   // output cols g4..g4+3

        u64 hmu[4] = {0ull, 0ull, 0ull, 0ull};
        u64 hsp[4] = {0ull, 0ull, 0ull, 0ull};

        #pragma unroll
        for (int k = 0; k < 14; k++) {
            const ulonglong2 v =
                *reinterpret_cast<const ulonglong2*>(&vs[r][g4 + k][0]);  // LDS.128
            const u64 m = v.x;
            const u64 s = v.y;
            #pragma unroll
            for (int o = 0; o < 4; o++) {
                const int t = k - o;
                if (t >= 0 && t < 11) {
                    const u64 w2 = ldw2(t);
                    hmu[o] = fma2(m, w2, hmu[o]);
                    hsp[o] = fma2(s, w2, hsp[o]);
                }
            }
        }

        const float C1 = 6.5025f;    // (0.01*255)^2
        const float C2 = 58.5225f;   // (0.03*255)^2
        const float SCALE = 0.000244140625f;  // 2^-12: keep 4-products in range

        float nn[4], dd[4];
        #pragma unroll
        for (int o = 0; o < 4; o++) {
            if (by + r < H && bx + g4 + o < W) {
                float mu1, mu2, sqs, exy;
                unpack2(hmu[o], mu1, mu2);
                unpack2(hsp[o], sqs, exy);   // sqs = G(xx)+G(yy), exy = G(xy)
                const float m11  = mu1 * mu1;
                const float m22  = mu2 * mu2;
                const float m12  = mu1 * mu2;
                const float msum = m11 + m22;
                const float s12  = exy - m12;
                const float ssum = sqs - msum;        // sigma1^2 + sigma2^2
                nn[o] = ((2.f * m12 + C1) * SCALE) * ((2.f * s12 + C2) * SCALE);
                dd[o] = ((msum + C1) * SCALE) * ((ssum + C2) * SCALE);
            } else {
                nn[o] = 0.f;
                dd[o] = 1.f;
            }
        }
        // sum_i n_i/d_i = (sum_i n_i * prod_{j!=i} d_j) / prod_j d_j -> one RCP / 4 px
        const float d01 = dd[0] * dd[1];
        const float d23 = dd[2] * dd[3];
        const float D   = d01 * d23;
        const float s01 = fmaf(nn[0], dd[1], nn[1] * dd[0]);
        const float s23 = fmaf(nn[2], dd[3], nn[3] * dd[2]);
        const float S   = fmaf(s01, d23, s23 * d01);
        lsum = __fdividef(S, D);
    }

    // ---------------- block reduction ----------------
    #pragma unroll
    for (int off = 16; off; off >>= 1)
        lsum += __shfl_xor_sync(0xffffffffu, lsum, off);
    if ((tid & 31) == 0) wsum[tid >> 5] = lsum;
    __syncthreads();
    if (tid == 0) {
        float s = 0.f;
        #pragma unroll
        for (int w = 0; w < NTHREADS / 32; w++) s += wsum[w];
        g_blockSums[blockIdx.y * gridDim.x + blockIdx.x] = s;
        __threadfence();
        unsigned int prev = atomicAdd(&g_count, 1u);
        isLast = (prev == (unsigned int)(nBlocks - 1));
    }
    __syncthreads();

    // ---------------- last block: final deterministic reduce ----------------
    if (isLast) {
        // reuse vs storage for the double scratch (all vs uses are done)
        double* dsm = reinterpret_cast<double*>(&vs[0][0][0]);
        double acc = 0.0;
        if ((nBlocks & 3) == 0) {
            const float4* p = (const float4*)g_blockSums;
            const int n4 = nBlocks >> 2;
            for (int i = tid; i < n4; i += NTHREADS) {
                float4 v = p[i];
                acc += (double)v.x + (double)v.y + (double)v.z + (double)v.w;
            }
        } else {
            for (int i = tid; i < nBlocks; i += NTHREADS)
                acc += (double)g_blockSums[i];
        }
        dsm[tid] = acc;
        __syncthreads();
        #pragma unroll
        for (int s = NTHREADS / 2; s; s >>= 1) {
            if (tid < s) dsm[tid] += dsm[tid + s];
            __syncthreads();
        }
        if (tid == 0) {
            out[0] = (float)(dsm[0] * inv_n);
            g_count = 0;   // reset for next graph replay (deterministic)
        }
    }
}

extern "C" void kernel_launch(void* const* d_in, const int* in_sizes, int n_in,
                              void* d_out, int out_size)
{
    (void)n_in; (void)out_size;
    const float* img1 = (const float*)d_in[0];
    const float* img2 = (const float*)d_in[1];

    const long long n = (long long)in_sizes[0];
    int W = (int)(sqrt((double)n) + 0.5);
    if (W <= 0) W = 1;
    int H = (int)(n / W);

    dim3 grid((W + TILE_W - 1) / TILE_W, (H + TILE_H - 1) / TILE_H);
    const int nb = (int)(grid.x * grid.y);
    const double inv_n = 1.0 / ((double)H * (double)W);
    ssim_tile_kernel<<<grid, NTHREADS>>>(img1, img2, W, H, nb, inv_n,
                                         (float*)d_out);
}